// round 3
// baseline (speedup 1.0000x reference)
#include <cuda_runtime.h>
#include <math.h>

#define N_SAMP  400000
#define XDIMC   128
#define TPB     256
#define NBLK    ((N_SAMP + TPB - 1) / TPB)   /* 1563 */
#define NPAY    41
#define DSHIFT  11.313708f

// ---------------- scratch ----------------------------------------------------
__device__ float g_z[3 * N_SAMP];            // SoA: [z1 | dcos | deuc]
__device__ float g_part1[NBLK * NPAY];
__device__ float g_part3[NBLK];
__device__ float g_G[256], g_wb[16], g_bb[1];
__device__ float g_loss1[1];
__device__ float g_B[6], g_beta[3], g_alpha[1], g_loss3[1];

// ---------------- packed f32x2 + fast math helpers ---------------------------
#define FMA_F32X2(d, a, b, c) \
    asm("fma.rn.f32x2 %0, %1, %2, %3;" : "=l"(d) : "l"(a), "l"(b), "l"(c))
#define DUP_F32X2(d, x) \
    asm("mov.b64 %0, {%1, %1};" : "=l"(d) : "f"(x))
#define PACK_F32X2(d, lo, hi) \
    asm("mov.b64 %0, {%1, %2};" : "=l"(d) : "f"(lo), "f"(hi))
#define UNPACK_F32X2(lo, hi, v) \
    asm("mov.b64 {%0, %1}, %2;" : "=f"(lo), "=f"(hi) : "l"(v))

__device__ __forceinline__ float tanh_fast(float x) {
    float y;
    asm("tanh.approx.f32 %0, %1;" : "=f"(y) : "f"(x));
    return y;
}

// ---------------- deterministic block reduction (8 warps) ---------------------
template <int V>
__device__ __forceinline__ void block_reduce8(float (&vals)[V], float* red, float* out) {
    int lane = threadIdx.x & 31;
    int wid  = threadIdx.x >> 5;
#pragma unroll
    for (int v = 0; v < V; v++) {
        float x = vals[v];
#pragma unroll
        for (int o = 16; o > 0; o >>= 1) x += __shfl_down_sync(0xffffffffu, x, o);
        vals[v] = x;
    }
    if (lane == 0) {
#pragma unroll
        for (int v = 0; v < V; v++) red[wid * V + v] = vals[v];
    }
    __syncthreads();
    if ((int)threadIdx.x < V) {
        float s = 0.f;
#pragma unroll
        for (int w = 0; w < 8; w++) s += red[w * V + threadIdx.x];
        out[threadIdx.x] = s;
    }
}

// ---------------- K0: Gram of dec_w3, wb, bb ---------------------------------
__global__ void k_prep(const float* __restrict__ dw3, const float* __restrict__ db3) {
    int tid = threadIdx.x;
    if (tid < 256) {
        int j = tid >> 4, k = tid & 15;
        float s = 0.f;
        for (int i = 0; i < 128; i++) s = fmaf(dw3[j * 128 + i], dw3[k * 128 + i], s);
        g_G[tid] = s;
    }
    if (tid < 16) {
        float s = 0.f;
        for (int i = 0; i < 128; i++) s = fmaf(dw3[tid * 128 + i], db3[i], s);
        g_wb[tid] = s;
    }
    if (tid == 0) {
        float s = 0.f;
        for (int i = 0; i < 128; i++) s = fmaf(db3[i], db3[i], s);
        g_bb[0] = s;
    }
}

// ---------------- K1: heavy fused pass (flat, one thread = one sample) -------
__global__ __launch_bounds__(TPB, 2) void k_passA(
    const float* __restrict__ x1,
    const float* __restrict__ ew1, const float* __restrict__ eb1,
    const float* __restrict__ ew2, const float* __restrict__ eb2,
    const float* __restrict__ ew3, const float* __restrict__ eb3,
    const float* __restrict__ dw1, const float* __restrict__ db1,
    const float* __restrict__ dw2, const float* __restrict__ db2,
    const float* __restrict__ dw3, const float* __restrict__ db3,
    const float* __restrict__ tw1, const float* __restrict__ tb1,
    const float* __restrict__ tw2, const float* __restrict__ tb2)
{
    // s_w[k][32]: interleaved pairs (ew1[k][j], dw3T[k][j]) for j=0..15
    __shared__ __align__(16) float s_w[128 * 32];
    __shared__ float s_b3[128];
    __shared__ float s_eb1[16], s_ew2[16 * 8], s_eb2[8], s_ew3[8], s_eb3[1];
    __shared__ float s_dw1[8], s_db1[8], s_dw2[8 * 16], s_db2[16];
    __shared__ float s_G[256], s_wb[16], s_bb[1];
    __shared__ float s_tw1[24], s_tb1[8], s_tw2[32], s_tb2[4];
    __shared__ float s_red[8 * NPAY];

    int tid = threadIdx.x;
    for (int idx = tid; idx < 2048; idx += TPB) {
        int k = idx >> 4, j = idx & 15;
        s_w[k * 32 + 2 * j] = ew1[idx];                 // ew1 is [128][16]
    }
    for (int idx = tid; idx < 2048; idx += TPB) {
        int j = idx >> 7, k = idx & 127;
        s_w[k * 32 + 2 * j + 1] = dw3[idx];             // dw3 is [16][128]
    }
    if (tid < 128) s_b3[tid] = db3[tid];
    if (tid < 16)  s_eb1[tid] = eb1[tid];
    if (tid < 128) s_ew2[tid] = ew2[tid];
    if (tid < 8)   s_eb2[tid] = eb2[tid];
    if (tid < 8)   s_ew3[tid] = ew3[tid];
    if (tid == 0)  s_eb3[0]   = eb3[0];
    if (tid < 8)   s_dw1[tid] = dw1[tid];
    if (tid < 8)   s_db1[tid] = db1[tid];
    if (tid < 128) s_dw2[tid] = dw2[tid];
    if (tid < 16)  s_db2[tid] = db2[tid];
    s_G[tid] = g_G[tid];
    if (tid < 16)  s_wb[tid]  = g_wb[tid];
    if (tid == 0)  s_bb[0]    = g_bb[0];
    if (tid < 24)  s_tw1[tid] = tw1[tid];
    if (tid < 8)   s_tb1[tid] = tb1[tid];
    if (tid < 32)  s_tw2[tid] = tw2[tid];
    if (tid < 4)   s_tb2[tid] = tb2[tid];
    __syncthreads();

    int n = blockIdx.x * TPB + tid;
    float r[NPAY];
#pragma unroll
    for (int v = 0; v < NPAY; v++) r[v] = 0.f;

    if (n < N_SAMP) {
        const float* xrow = x1 + (size_t)n * XDIMC;

        unsigned long long acc[16];      // pair j = (u[j], vv[j])
        unsigned long long stacc;        // (s = x.x, t = x.b3)
#pragma unroll
        for (int j = 0; j < 16; j++) acc[j] = 0ull;
        stacc = 0ull;

#pragma unroll 1
        for (int i0 = 0; i0 < XDIMC; i0 += 8) {
            float4 xa = *reinterpret_cast<const float4*>(xrow + i0);
            float4 xb = *reinterpret_cast<const float4*>(xrow + i0 + 4);
            float xs[8] = { xa.x, xa.y, xa.z, xa.w, xb.x, xb.y, xb.z, xb.w };
#pragma unroll
            for (int c = 0; c < 8; c++) {
                float xv = xs[c];
                int k = i0 + c;
                unsigned long long xd, stm;
                DUP_F32X2(xd, xv);
                PACK_F32X2(stm, xv, s_b3[k]);
                FMA_F32X2(stacc, xd, stm, stacc);
                const unsigned long long* wp =
                    reinterpret_cast<const unsigned long long*>(s_w + k * 32);
#pragma unroll
                for (int j = 0; j < 16; j++) {
                    FMA_F32X2(acc[j], xd, wp[j], acc[j]);
                }
            }
        }

        float u[16], vv[16];
#pragma unroll
        for (int j = 0; j < 16; j++) UNPACK_F32X2(u[j], vv[j], acc[j]);
        float s, t;
        UNPACK_F32X2(s, t, stacc);

        // encoder tail
        float a[16];
#pragma unroll
        for (int j = 0; j < 16; j++) a[j] = tanh_fast(u[j] + s_eb1[j]);
        float h2[8];
#pragma unroll
        for (int k = 0; k < 8; k++) {
            float e = s_eb2[k];
#pragma unroll
            for (int j = 0; j < 16; j++) e = fmaf(a[j], s_ew2[j * 8 + k], e);
            h2[k] = tanh_fast(e);
        }
        float z1a = s_eb3[0];
#pragma unroll
        for (int k = 0; k < 8; k++) z1a = fmaf(h2[k], s_ew3[k], z1a);
        float z1 = tanh_fast(z1a);

        // decoder to d2[16]; x2 never materialized
        float d1[8];
#pragma unroll
        for (int k = 0; k < 8; k++) d1[k] = tanh_fast(fmaf(z1, s_dw1[k], s_db1[k]));
        float d2[16];
#pragma unroll
        for (int j = 0; j < 16; j++) {
            float e = s_db2[j];
#pragma unroll
            for (int k = 0; k < 8; k++) e = fmaf(d1[k], s_dw2[k * 16 + j], e);
            d2[j] = tanh_fast(e);
        }

        // distances via Gram trick
        float hv = 0.f, hwb = 0.f, hGh = 0.f;
#pragma unroll
        for (int j = 0; j < 16; j++) {
            hv  = fmaf(d2[j], vv[j], hv);
            hwb = fmaf(d2[j], s_wb[j], hwb);
            float gj = 0.f;
#pragma unroll
            for (int k = 0; k < 16; k++) gj = fmaf(s_G[j * 16 + k], d2[k], gj);
            hGh = fmaf(d2[j], gj, hGh);
        }
        float x1x2  = hv + t;
        float n2    = hGh + 2.f * hwb + s_bb[0];
        float eucsq = s - 2.f * x1x2 + n2;
        float deuc  = sqrtf(fmaxf(eucsq, 0.f));
        float dcos  = x1x2 * rsqrtf(s * n2);

        // estimator -> softmax
        float e1[8];
#pragma unroll
        for (int k = 0; k < 8; k++) {
            float e = s_tb1[k];
            e = fmaf(z1,   s_tw1[k],      e);
            e = fmaf(dcos, s_tw1[8 + k],  e);
            e = fmaf(deuc, s_tw1[16 + k], e);
            e1[k] = tanh_fast(e);
        }
        float lg[4];
#pragma unroll
        for (int q = 0; q < 4; q++) {
            float e = s_tb2[q];
#pragma unroll
            for (int k = 0; k < 8; k++) e = fmaf(e1[k], s_tw2[k * 4 + q], e);
            lg[q] = e;
        }
        float m = fmaxf(fmaxf(lg[0], lg[1]), fmaxf(lg[2], lg[3]));
        float ex0 = __expf(lg[0] - m), ex1 = __expf(lg[1] - m);
        float ex2 = __expf(lg[2] - m), ex3 = __expf(lg[3] - m);
        float inv = 1.f / (ex0 + ex1 + ex2 + ex3);
        float gam[4] = { ex0 * inv, ex1 * inv, ex2 * inv, ex3 * inv };

        // outputs (SoA, coalesced)
        g_z[n]              = z1;
        g_z[N_SAMP + n]     = dcos;
        g_z[2 * N_SAMP + n] = deuc;

        // reduction payload: gamma, gamma*z_shifted, eucsq, gamma*outer(z_shifted)
        float zc0 = z1, zc1 = dcos, zc2 = deuc - DSHIFT;
        float zz[6] = { zc0 * zc0, zc0 * zc1, zc0 * zc2,
                        zc1 * zc1, zc1 * zc2, zc2 * zc2 };
#pragma unroll
        for (int q = 0; q < 4; q++) {
            r[q] = gam[q];
            r[4 + q * 3 + 0] = gam[q] * zc0;
            r[4 + q * 3 + 1] = gam[q] * zc1;
            r[4 + q * 3 + 2] = gam[q] * zc2;
#pragma unroll
            for (int mmi = 0; mmi < 6; mmi++)
                r[17 + q * 6 + mmi] = gam[q] * zz[mmi];
        }
        r[16] = eucsq;
    }

    block_reduce8<NPAY>(r, s_red, &g_part1[blockIdx.x * NPAY]);
}

// ---------------- K2: reduce all partials -> GMM params ----------------------
__global__ __launch_bounds__(TPB) void k_reduceAll() {
    __shared__ float red[8 * NPAY];
    __shared__ float sfin[NPAY];
    float acc[NPAY];
#pragma unroll
    for (int v = 0; v < NPAY; v++) acc[v] = 0.f;
    for (int b = threadIdx.x; b < NBLK; b += TPB) {
#pragma unroll
        for (int v = 0; v < NPAY; v++) acc[v] += g_part1[b * NPAY + v];
    }
    block_reduce8<NPAY>(acc, red, sfin);
    __syncthreads();

    if (threadIdx.x == 0) {
        const float LOG_2PI = 1.8378770664093454f;
        float B0 = 0.f, B1 = 0.f, B2 = 0.f, B3 = 0.f, B4 = 0.f, B5 = 0.f;
        float be0 = 0.f, be1 = 0.f, be2 = 0.f, alpha = 0.f, l3 = 0.f;
        for (int k = 0; k < 4; k++) {
            float gs = sfin[k];
            float m0s = sfin[4 + k * 3 + 0] / gs;
            float m1s = sfin[4 + k * 3 + 1] / gs;
            float m2s = sfin[4 + k * 3 + 2] / gs;
            float a = sfin[17 + k * 6 + 0] / gs - m0s * m0s;
            float b = sfin[17 + k * 6 + 1] / gs - m0s * m1s;
            float c = sfin[17 + k * 6 + 2] / gs - m0s * m2s;
            float d = sfin[17 + k * 6 + 3] / gs - m1s * m1s;
            float e = sfin[17 + k * 6 + 4] / gs - m1s * m2s;
            float f = sfin[17 + k * 6 + 5] / gs - m2s * m2s;
            float m0 = m0s, m1 = m1s, m2 = m2s + DSHIFT;

            float det = a * (d * f - e * e) - b * (b * f - e * c) + c * (b * e - d * c);
            float id  = 1.f / det;
            float A00 = (d * f - e * e) * id, A01 = (c * e - b * f) * id, A02 = (b * e - c * d) * id;
            float A11 = (a * f - c * c) * id, A12 = (b * c - a * e) * id, A22 = (a * d - b * b) * id;
            float phi = gs / (float)N_SAMP;
            float ck  = logf(phi) - 0.5f * (3.f * LOG_2PI + logf(det));
            float Am0 = A00 * m0 + A01 * m1 + A02 * m2;
            float Am1 = A01 * m0 + A11 * m1 + A12 * m2;
            float Am2 = A02 * m0 + A12 * m1 + A22 * m2;
            float mAm = m0 * Am0 + m1 * Am1 + m2 * Am2;
            B0 += 0.5f * A00; B1 += 0.5f * A01; B2 += 0.5f * A02;
            B3 += 0.5f * A11; B4 += 0.5f * A12; B5 += 0.5f * A22;
            be0 -= Am0; be1 -= Am1; be2 -= Am2;
            alpha += -ck + 0.5f * mAm;
            l3 += 1.f / a + 1.f / d + 1.f / f;
        }
        g_B[0] = B0; g_B[1] = B1; g_B[2] = B2; g_B[3] = B3; g_B[4] = B4; g_B[5] = B5;
        g_beta[0] = be0; g_beta[1] = be1; g_beta[2] = be2;
        g_alpha[0] = alpha;
        g_loss3[0] = 0.0001f * l3;
        g_loss1[0] = sfin[16] / (float)N_SAMP;
    }
}

// ---------------- K3: per-sample energy + partial sums -----------------------
__global__ __launch_bounds__(TPB) void k_energy(float* __restrict__ out) {
    __shared__ float red[8];
    int n = blockIdx.x * TPB + threadIdx.x;
    float r = 0.f;
    if (n < N_SAMP) {
        float z0 = g_z[n], zc = g_z[N_SAMP + n], ze = g_z[2 * N_SAMP + n];
        float q = g_B[0] * z0 * z0 + g_B[3] * zc * zc + g_B[5] * ze * ze
                + 2.f * (g_B[1] * z0 * zc + g_B[2] * z0 * ze + g_B[4] * zc * ze);
        float en = g_alpha[0] + g_beta[0] * z0 + g_beta[1] * zc + g_beta[2] * ze + q;
        out[n] = en;
        r = en;
    }
    int lane = threadIdx.x & 31, wid = threadIdx.x >> 5;
#pragma unroll
    for (int o = 16; o > 0; o >>= 1) r += __shfl_down_sync(0xffffffffu, r, o);
    if (lane == 0) red[wid] = r;
    __syncthreads();
    if (threadIdx.x == 0) {
        float s = 0.f;
#pragma unroll
        for (int w = 0; w < 8; w++) s += red[w];
        g_part3[blockIdx.x] = s;
    }
}

// ---------------- K4: finalize loss ------------------------------------------
__global__ __launch_bounds__(TPB) void k_final(float* __restrict__ out, int out_size) {
    __shared__ float red[8];
    __shared__ float sfin[1];
    float acc[1];
    acc[0] = 0.f;
    for (int b = threadIdx.x; b < NBLK; b += TPB) acc[0] += g_part3[b];
    block_reduce8<1>(acc, red, sfin);
    __syncthreads();
    if (threadIdx.x == 0 && out_size > N_SAMP) {
        out[N_SAMP] = g_loss1[0] + 0.01f * (sfin[0] / (float)N_SAMP) + g_loss3[0];
    }
}

// ---------------- launch -----------------------------------------------------
extern "C" void kernel_launch(void* const* d_in, const int* in_sizes, int n_in,
                              void* d_out, int out_size) {
    const float* x1  = (const float*)d_in[0];
    const float* ew1 = (const float*)d_in[1];
    const float* eb1 = (const float*)d_in[2];
    const float* ew2 = (const float*)d_in[3];
    const float* eb2 = (const float*)d_in[4];
    const float* ew3 = (const float*)d_in[5];
    const float* eb3 = (const float*)d_in[6];
    const float* dw1 = (const float*)d_in[7];
    const float* db1 = (const float*)d_in[8];
    const float* dw2 = (const float*)d_in[9];
    const float* db2 = (const float*)d_in[10];
    const float* dw3 = (const float*)d_in[11];
    const float* db3 = (const float*)d_in[12];
    const float* tw1 = (const float*)d_in[13];
    const float* tb1 = (const float*)d_in[14];
    const float* tw2 = (const float*)d_in[15];
    const float* tb2 = (const float*)d_in[16];
    float* out = (float*)d_out;

    k_prep<<<1, 256>>>(dw3, db3);
    k_passA<<<NBLK, TPB>>>(x1, ew1, eb1, ew2, eb2, ew3, eb3,
                           dw1, db1, dw2, db2, dw3, db3,
                           tw1, tb1, tw2, tb2);
    k_reduceAll<<<1, TPB>>>();
    k_energy<<<NBLK, TPB>>>(out);
    k_final<<<1, TPB>>>(out, out_size);
}

// round 4
// speedup vs baseline: 1.6316x; 1.6316x over previous
#include <cuda_runtime.h>
#include <math.h>

#define N_SAMP  400000
#define XDIMC   128
#define TPB     256
#define NBLK    ((N_SAMP + TPB - 1) / TPB)   /* 1563 */
#define NPAY    41
#define DSHIFT  11.313708f

// ---------------- scratch ----------------------------------------------------
__device__ float g_z[3 * N_SAMP];            // SoA: [z1 | dcos | deuc]
__device__ float g_part1[NBLK * NPAY];
__device__ float g_part3[NBLK];
__device__ float g_G[256], g_wb[16], g_bb[1];
__device__ float g_loss1[1];
__device__ float g_B[6], g_beta[3], g_alpha[1], g_loss3[1];

// ---------------- fast accurate tanh: 1 - 2/(exp(2x)+1) ----------------------
__device__ __forceinline__ float tanh_e(float x) {
    float e = __expf(2.0f * x);              // inf for large x, 0 for very negative
    return 1.0f - __fdividef(2.0f, e + 1.0f);
}

// ---------------- deterministic block reduction (8 warps) ---------------------
template <int V>
__device__ __forceinline__ void block_reduce8(float (&vals)[V], float* red, float* out) {
    int lane = threadIdx.x & 31;
    int wid  = threadIdx.x >> 5;
#pragma unroll
    for (int v = 0; v < V; v++) {
        float x = vals[v];
#pragma unroll
        for (int o = 16; o > 0; o >>= 1) x += __shfl_down_sync(0xffffffffu, x, o);
        vals[v] = x;
    }
    if (lane == 0) {
#pragma unroll
        for (int v = 0; v < V; v++) red[wid * V + v] = vals[v];
    }
    __syncthreads();
    if ((int)threadIdx.x < V) {
        float s = 0.f;
#pragma unroll
        for (int w = 0; w < 8; w++) s += red[w * V + threadIdx.x];
        out[threadIdx.x] = s;
    }
}

// ---------------- K0: Gram of dec_w3, wb, bb ---------------------------------
__global__ void k_prep(const float* __restrict__ dw3, const float* __restrict__ db3) {
    int tid = threadIdx.x;
    if (tid < 256) {
        int j = tid >> 4, k = tid & 15;
        float s = 0.f;
        for (int i = 0; i < 128; i++) s = fmaf(dw3[j * 128 + i], dw3[k * 128 + i], s);
        g_G[tid] = s;
    }
    if (tid < 16) {
        float s = 0.f;
        for (int i = 0; i < 128; i++) s = fmaf(dw3[tid * 128 + i], db3[i], s);
        g_wb[tid] = s;
    }
    if (tid == 0) {
        float s = 0.f;
        for (int i = 0; i < 128; i++) s = fmaf(db3[i], db3[i], s);
        g_bb[0] = s;
    }
}

// ---------------- K1: heavy per-sample pass (Round-1 structure) --------------
__global__ __launch_bounds__(TPB) void k_passA(
    const float* __restrict__ x1,
    const float* __restrict__ ew1, const float* __restrict__ eb1,
    const float* __restrict__ ew2, const float* __restrict__ eb2,
    const float* __restrict__ ew3, const float* __restrict__ eb3,
    const float* __restrict__ dw1, const float* __restrict__ db1,
    const float* __restrict__ dw2, const float* __restrict__ db2,
    const float* __restrict__ dw3, const float* __restrict__ db3,
    const float* __restrict__ tw1, const float* __restrict__ tb1,
    const float* __restrict__ tw2, const float* __restrict__ tb2)
{
    __shared__ __align__(16) float s_ew1[128 * 16];
    __shared__ __align__(16) float s_dwT[128 * 16];   // dec_w3 transposed: [i][j]
    __shared__ float s_b3[128];
    __shared__ float s_eb1[16], s_ew2[16 * 8], s_eb2[8], s_ew3[8], s_eb3[1];
    __shared__ float s_dw1[8], s_db1[8], s_dw2[8 * 16], s_db2[16];
    __shared__ float s_G[256], s_wb[16], s_bb[1];
    __shared__ float s_tw1[24], s_tb1[8], s_tw2[32], s_tb2[4];
    __shared__ float s_red[8 * NPAY];

    int tid = threadIdx.x;
    for (int idx = tid; idx < 2048; idx += TPB) s_ew1[idx] = ew1[idx];
    for (int idx = tid; idx < 2048; idx += TPB) {
        int j = idx >> 7, i = idx & 127;
        s_dwT[i * 16 + j] = dw3[idx];
    }
    if (tid < 128) s_b3[tid] = db3[tid];
    if (tid < 16)  s_eb1[tid] = eb1[tid];
    if (tid < 128) s_ew2[tid] = ew2[tid];
    if (tid < 8)   s_eb2[tid] = eb2[tid];
    if (tid < 8)   s_ew3[tid] = ew3[tid];
    if (tid == 0)  s_eb3[0]   = eb3[0];
    if (tid < 8)   s_dw1[tid] = dw1[tid];
    if (tid < 8)   s_db1[tid] = db1[tid];
    if (tid < 128) s_dw2[tid] = dw2[tid];
    if (tid < 16)  s_db2[tid] = db2[tid];
    s_G[tid] = g_G[tid];
    if (tid < 16)  s_wb[tid]  = g_wb[tid];
    if (tid == 0)  s_bb[0]    = g_bb[0];
    if (tid < 24)  s_tw1[tid] = tw1[tid];
    if (tid < 8)   s_tb1[tid] = tb1[tid];
    if (tid < 32)  s_tw2[tid] = tw2[tid];
    if (tid < 4)   s_tb2[tid] = tb2[tid];
    __syncthreads();

    int n = blockIdx.x * TPB + tid;
    float r[NPAY];
#pragma unroll
    for (int v = 0; v < NPAY; v++) r[v] = 0.f;

    if (n < N_SAMP) {
        const float* xrow = x1 + (size_t)n * XDIMC;
        float u[16], vv[16];
#pragma unroll
        for (int j = 0; j < 16; j++) { u[j] = 0.f; vv[j] = 0.f; }
        float s = 0.f, t = 0.f;

#pragma unroll 1
        for (int i0 = 0; i0 < XDIMC; i0 += 8) {
            float4 xa = *reinterpret_cast<const float4*>(xrow + i0);
            float4 xb = *reinterpret_cast<const float4*>(xrow + i0 + 4);
            float xs[8] = { xa.x, xa.y, xa.z, xa.w, xb.x, xb.y, xb.z, xb.w };
#pragma unroll
            for (int c = 0; c < 8; c++) {
                float xv = xs[c];
                int row = i0 + c;
                const float4* wp1 = reinterpret_cast<const float4*>(s_ew1 + row * 16);
                const float4* wp2 = reinterpret_cast<const float4*>(s_dwT + row * 16);
#pragma unroll
                for (int q = 0; q < 4; q++) {
                    float4 wa = wp1[q];
                    float4 wb4 = wp2[q];
                    u[4 * q + 0] = fmaf(xv, wa.x, u[4 * q + 0]);
                    u[4 * q + 1] = fmaf(xv, wa.y, u[4 * q + 1]);
                    u[4 * q + 2] = fmaf(xv, wa.z, u[4 * q + 2]);
                    u[4 * q + 3] = fmaf(xv, wa.w, u[4 * q + 3]);
                    vv[4 * q + 0] = fmaf(xv, wb4.x, vv[4 * q + 0]);
                    vv[4 * q + 1] = fmaf(xv, wb4.y, vv[4 * q + 1]);
                    vv[4 * q + 2] = fmaf(xv, wb4.z, vv[4 * q + 2]);
                    vv[4 * q + 3] = fmaf(xv, wb4.w, vv[4 * q + 3]);
                }
                s = fmaf(xv, xv, s);
                t = fmaf(xv, s_b3[row], t);
            }
        }

        // encoder tail
        float a[16];
#pragma unroll
        for (int j = 0; j < 16; j++) a[j] = tanh_e(u[j] + s_eb1[j]);
        float h2[8];
#pragma unroll
        for (int k = 0; k < 8; k++) {
            float acc = s_eb2[k];
#pragma unroll
            for (int j = 0; j < 16; j++) acc = fmaf(a[j], s_ew2[j * 8 + k], acc);
            h2[k] = tanh_e(acc);
        }
        float z1a = s_eb3[0];
#pragma unroll
        for (int k = 0; k < 8; k++) z1a = fmaf(h2[k], s_ew3[k], z1a);
        float z1 = tanh_e(z1a);

        // decoder to d2[16]; x2 never materialized
        float d1[8];
#pragma unroll
        for (int k = 0; k < 8; k++) d1[k] = tanh_e(fmaf(z1, s_dw1[k], s_db1[k]));
        float d2[16];
#pragma unroll
        for (int j = 0; j < 16; j++) {
            float acc = s_db2[j];
#pragma unroll
            for (int k = 0; k < 8; k++) acc = fmaf(d1[k], s_dw2[k * 16 + j], acc);
            d2[j] = tanh_e(acc);
        }

        // distances via Gram trick
        float hv = 0.f, hwb = 0.f, hGh = 0.f;
#pragma unroll
        for (int j = 0; j < 16; j++) {
            hv  = fmaf(d2[j], vv[j], hv);
            hwb = fmaf(d2[j], s_wb[j], hwb);
            float gj = 0.f;
#pragma unroll
            for (int k = 0; k < 16; k++) gj = fmaf(s_G[j * 16 + k], d2[k], gj);
            hGh = fmaf(d2[j], gj, hGh);
        }
        float x1x2  = hv + t;
        float n2    = hGh + 2.f * hwb + s_bb[0];
        float eucsq = s - 2.f * x1x2 + n2;
        float deuc  = sqrtf(fmaxf(eucsq, 0.f));
        float dcos  = x1x2 * rsqrtf(s * n2);

        // estimator -> softmax
        float e1[8];
#pragma unroll
        for (int k = 0; k < 8; k++) {
            float acc = s_tb1[k];
            acc = fmaf(z1,   s_tw1[k],      acc);
            acc = fmaf(dcos, s_tw1[8 + k],  acc);
            acc = fmaf(deuc, s_tw1[16 + k], acc);
            e1[k] = tanh_e(acc);
        }
        float lg[4];
#pragma unroll
        for (int q = 0; q < 4; q++) {
            float acc = s_tb2[q];
#pragma unroll
            for (int k = 0; k < 8; k++) acc = fmaf(e1[k], s_tw2[k * 4 + q], acc);
            lg[q] = acc;
        }
        float m = fmaxf(fmaxf(lg[0], lg[1]), fmaxf(lg[2], lg[3]));
        float ex0 = __expf(lg[0] - m), ex1 = __expf(lg[1] - m);
        float ex2 = __expf(lg[2] - m), ex3 = __expf(lg[3] - m);
        float inv = 1.f / (ex0 + ex1 + ex2 + ex3);
        float gam[4] = { ex0 * inv, ex1 * inv, ex2 * inv, ex3 * inv };

        // outputs (SoA, coalesced)
        g_z[n]              = z1;
        g_z[N_SAMP + n]     = dcos;
        g_z[2 * N_SAMP + n] = deuc;

        // reduction payload: gamma, gamma*z_shifted, eucsq, gamma*outer(z_shifted)
        float zc0 = z1, zc1 = dcos, zc2 = deuc - DSHIFT;
        float zz[6] = { zc0 * zc0, zc0 * zc1, zc0 * zc2,
                        zc1 * zc1, zc1 * zc2, zc2 * zc2 };
#pragma unroll
        for (int q = 0; q < 4; q++) {
            r[q] = gam[q];
            r[4 + q * 3 + 0] = gam[q] * zc0;
            r[4 + q * 3 + 1] = gam[q] * zc1;
            r[4 + q * 3 + 2] = gam[q] * zc2;
#pragma unroll
            for (int mmi = 0; mmi < 6; mmi++)
                r[17 + q * 6 + mmi] = gam[q] * zz[mmi];
        }
        r[16] = eucsq;
    }

    block_reduce8<NPAY>(r, s_red, &g_part1[blockIdx.x * NPAY]);
}

// ---------------- K2: reduce all partials -> GMM params ----------------------
__global__ __launch_bounds__(TPB) void k_reduceAll() {
    __shared__ float red[8 * NPAY];
    __shared__ float sfin[NPAY];
    float acc[NPAY];
#pragma unroll
    for (int v = 0; v < NPAY; v++) acc[v] = 0.f;
    for (int b = threadIdx.x; b < NBLK; b += TPB) {
#pragma unroll
        for (int v = 0; v < NPAY; v++) acc[v] += g_part1[b * NPAY + v];
    }
    block_reduce8<NPAY>(acc, red, sfin);
    __syncthreads();

    if (threadIdx.x == 0) {
        const float LOG_2PI = 1.8378770664093454f;
        float B0 = 0.f, B1 = 0.f, B2 = 0.f, B3 = 0.f, B4 = 0.f, B5 = 0.f;
        float be0 = 0.f, be1 = 0.f, be2 = 0.f, alpha = 0.f, l3 = 0.f;
        for (int k = 0; k < 4; k++) {
            float gs = sfin[k];
            float m0s = sfin[4 + k * 3 + 0] / gs;
            float m1s = sfin[4 + k * 3 + 1] / gs;
            float m2s = sfin[4 + k * 3 + 2] / gs;
            float a = sfin[17 + k * 6 + 0] / gs - m0s * m0s;
            float b = sfin[17 + k * 6 + 1] / gs - m0s * m1s;
            float c = sfin[17 + k * 6 + 2] / gs - m0s * m2s;
            float d = sfin[17 + k * 6 + 3] / gs - m1s * m1s;
            float e = sfin[17 + k * 6 + 4] / gs - m1s * m2s;
            float f = sfin[17 + k * 6 + 5] / gs - m2s * m2s;
            float m0 = m0s, m1 = m1s, m2 = m2s + DSHIFT;

            float det = a * (d * f - e * e) - b * (b * f - e * c) + c * (b * e - d * c);
            float id  = 1.f / det;
            float A00 = (d * f - e * e) * id, A01 = (c * e - b * f) * id, A02 = (b * e - c * d) * id;
            float A11 = (a * f - c * c) * id, A12 = (b * c - a * e) * id, A22 = (a * d - b * b) * id;
            float phi = gs / (float)N_SAMP;
            float ck  = logf(phi) - 0.5f * (3.f * LOG_2PI + logf(det));
            float Am0 = A00 * m0 + A01 * m1 + A02 * m2;
            float Am1 = A01 * m0 + A11 * m1 + A12 * m2;
            float Am2 = A02 * m0 + A12 * m1 + A22 * m2;
            float mAm = m0 * Am0 + m1 * Am1 + m2 * Am2;
            B0 += 0.5f * A00; B1 += 0.5f * A01; B2 += 0.5f * A02;
            B3 += 0.5f * A11; B4 += 0.5f * A12; B5 += 0.5f * A22;
            be0 -= Am0; be1 -= Am1; be2 -= Am2;
            alpha += -ck + 0.5f * mAm;
            l3 += 1.f / a + 1.f / d + 1.f / f;
        }
        g_B[0] = B0; g_B[1] = B1; g_B[2] = B2; g_B[3] = B3; g_B[4] = B4; g_B[5] = B5;
        g_beta[0] = be0; g_beta[1] = be1; g_beta[2] = be2;
        g_alpha[0] = alpha;
        g_loss3[0] = 0.0001f * l3;
        g_loss1[0] = sfin[16] / (float)N_SAMP;
    }
}

// ---------------- K3: per-sample energy + partial sums -----------------------
__global__ __launch_bounds__(TPB) void k_energy(float* __restrict__ out) {
    __shared__ float red[8];
    int n = blockIdx.x * TPB + threadIdx.x;
    float r = 0.f;
    if (n < N_SAMP) {
        float z0 = g_z[n], zc = g_z[N_SAMP + n], ze = g_z[2 * N_SAMP + n];
        float q = g_B[0] * z0 * z0 + g_B[3] * zc * zc + g_B[5] * ze * ze
                + 2.f * (g_B[1] * z0 * zc + g_B[2] * z0 * ze + g_B[4] * zc * ze);
        float en = g_alpha[0] + g_beta[0] * z0 + g_beta[1] * zc + g_beta[2] * ze + q;
        out[n] = en;
        r = en;
    }
    int lane = threadIdx.x & 31, wid = threadIdx.x >> 5;
#pragma unroll
    for (int o = 16; o > 0; o >>= 1) r += __shfl_down_sync(0xffffffffu, r, o);
    if (lane == 0) red[wid] = r;
    __syncthreads();
    if (threadIdx.x == 0) {
        float s = 0.f;
#pragma unroll
        for (int w = 0; w < 8; w++) s += red[w];
        g_part3[blockIdx.x] = s;
    }
}

// ---------------- K4: finalize loss ------------------------------------------
__global__ __launch_bounds__(TPB) void k_final(float* __restrict__ out, int out_size) {
    __shared__ float red[8];
    __shared__ float sfin[1];
    float acc[1];
    acc[0] = 0.f;
    for (int b = threadIdx.x; b < NBLK; b += TPB) acc[0] += g_part3[b];
    block_reduce8<1>(acc, red, sfin);
    __syncthreads();
    if (threadIdx.x == 0 && out_size > N_SAMP) {
        out[N_SAMP] = g_loss1[0] + 0.01f * (sfin[0] / (float)N_SAMP) + g_loss3[0];
    }
}

// ---------------- launch -----------------------------------------------------
extern "C" void kernel_launch(void* const* d_in, const int* in_sizes, int n_in,
                              void* d_out, int out_size) {
    const float* x1  = (const float*)d_in[0];
    const float* ew1 = (const float*)d_in[1];
    const float* eb1 = (const float*)d_in[2];
    const float* ew2 = (const float*)d_in[3];
    const float* eb2 = (const float*)d_in[4];
    const float* ew3 = (const float*)d_in[5];
    const float* eb3 = (const float*)d_in[6];
    const float* dw1 = (const float*)d_in[7];
    const float* db1 = (const float*)d_in[8];
    const float* dw2 = (const float*)d_in[9];
    const float* db2 = (const float*)d_in[10];
    const float* dw3 = (const float*)d_in[11];
    const float* db3 = (const float*)d_in[12];
    const float* tw1 = (const float*)d_in[13];
    const float* tb1 = (const float*)d_in[14];
    const float* tw2 = (const float*)d_in[15];
    const float* tb2 = (const float*)d_in[16];
    float* out = (float*)d_out;

    k_prep<<<1, 256>>>(dw3, db3);
    k_passA<<<NBLK, TPB>>>(x1, ew1, eb1, ew2, eb2, ew3, eb3,
                           dw1, db1, dw2, db2, dw3, db3,
                           tw1, tb1, tw2, tb2);
    k_reduceAll<<<1, TPB>>>();
    k_energy<<<NBLK, TPB>>>(out);
    k_final<<<1, TPB>>>(out, out_size);
}